// round 9
// baseline (speedup 1.0000x reference)
#include <cuda_runtime.h>

namespace {
constexpr int Bn=2, C0=64, Hn=160, Wn=160, DW=128;
constexpr int HW=Hn*Wn, NPOS=Bn*HW;
constexpr int Hp=162, Wp=162;
constexpr int VP_PER_B=Hp*Wp*DW;
constexpr int VP_PER_SIDE=Bn*VP_PER_B;
constexpr int H_PER_SIDE=NPOS*DW;
constexpr int OM_PER_SIDE=NPOS*108;
constexpr int F_PER_SIDE=NPOS*64;
}

__device__ __align__(16) float g_h [2*H_PER_SIDE];
__device__ __align__(16) float g_vp[2*VP_PER_SIDE];
__device__ __align__(16) float g_om[2*OM_PER_SIDE];
__device__ __align__(16) float g_f [2*F_PER_SIDE];
__device__ __align__(16) float g_part[2*Bn*40*64];
__device__ __align__(16) float g_scale[Bn*128];
__device__ __align__(16) float g_pw1T [64*128];
__device__ __align__(16) float g_valT [128*128];
__device__ __align__(16) float g_omT  [128*112];
__device__ __align__(16) float g_outpT[128*128];
__device__ __align__(16) float g_c3T  [128*64];
__device__ __align__(16) float g_c4T  [128*128];
__device__ __align__(16) float g_c5T  [64*64];

// register-tile GEMM: acc[TO][TP] += wT[c*ldo+o0+i] * xs[c*ldp+p0+j]
template<int C,int TO,int TP>
__device__ __forceinline__ void gemm(const float* __restrict__ wT,int ldo,
                                     const float* __restrict__ xs,int ldp,
                                     int o0,int p0,float acc[TO][TP]){
  #pragma unroll 4
  for(int c=0;c<C;++c){
    float wr[TO],xv[TP];
    #pragma unroll
    for(int i=0;i<TO;++i) wr[i]=wT[c*ldo+o0+i];
    #pragma unroll
    for(int j=0;j<TP;++j) xv[j]=xs[c*ldp+p0+j];
    #pragma unroll
    for(int i=0;i<TO;++i)
      #pragma unroll
      for(int j=0;j<TP;++j) acc[i][j]=fmaf(wr[i],xv[j],acc[i][j]);
  }
}

__global__ void prep_kernel(const float* __restrict__ pw1_w,const float* __restrict__ val_w,
                            const float* __restrict__ om_w,const float* __restrict__ outp_w,
                            const float* __restrict__ c3_w,const float* __restrict__ c4_w,
                            const float* __restrict__ c5_w){
  int i=blockIdx.x*256+threadIdx.x;
  if(i<8192){int o=i>>6,c=i&63; g_pw1T[c*128+o]=pw1_w[i]; return;} i-=8192;
  if(i<16384){int o=i>>7,c=i&127; g_valT[c*128+o]=val_w[i]; return;} i-=16384;
  if(i<14336){int o=i/128,c=i%128; g_omT[c*112+o]=om_w[i]; return;} i-=14336;
  if(i<16384){int o=i>>7,c=i&127; g_outpT[c*128+o]=outp_w[i]; return;} i-=16384;
  if(i<8192){int o=i>>7,c=i&127; g_c3T[c*64+o]=c3_w[i]; return;} i-=8192;
  if(i<16384){int o=i>>7,c=i&127; g_c4T[c*128+o]=c4_w[i]; return;} i-=16384;
  if(i<4096){int o=i>>6,c=i&63; g_c5T[c*64+o]=c5_w[i];}
}

__global__ void zero_borders_kernel(){
  constexpr int CELLS=2*162+2*160;  // 644
  int i=blockIdx.x*256+threadIdx.x;
  if(i>=4*CELLS*128) return;
  int sb=i/(CELLS*128), r=i%(CELLS*128), cell=r>>7, c=r&127;
  int y,x;
  if(cell<162){y=0;x=cell;}
  else if(cell<324){y=161;x=cell-162;}
  else if(cell<484){y=cell-324+1;x=0;}
  else{y=cell-484+1;x=161;}
  int side=sb>>1,b=sb&1;
  g_vp[(size_t)side*VP_PER_SIDE+(size_t)b*VP_PER_B+((size_t)y*Wp+x)*DW+c]=0.f;
}

// K1: LN(64) -> pw1(64->128) -> val(128->128), 32 pos/block
__global__ void __launch_bounds__(128)
k1(const float* __restrict__ xl,const float* __restrict__ xr,
   const float* __restrict__ ln1_g,const float* __restrict__ pw1_b,
   const float* __restrict__ val_b){
  const int side=blockIdx.z>>1, b=blockIdx.z&1, h=blockIdx.y, w0=blockIdx.x*32;
  const int tid=threadIdx.x;
  const float* __restrict__ x = side?xr:xl;
  __shared__ __align__(16) float xs[64*36];
  __shared__ __align__(16) float hs[128*36];
  __shared__ float mu[32],rsd[32];
  for(int i=tid;i<64*32;i+=128){
    int c=i>>5,p=i&31;
    xs[c*36+p]=x[((size_t)(b*64+c)*Hn+h)*Wn+w0+p];
  }
  __syncthreads();
  if(tid<32){
    float s=0.f,q=0.f;
    #pragma unroll
    for(int c=0;c<64;c++){float v=xs[c*36+tid];s+=v;q+=v*v;}
    float m=s*(1.f/64.f), var=q*(1.f/64.f)-m*m;
    mu[tid]=m; rsd[tid]=rsqrtf(var+1e-5f);
  }
  __syncthreads();
  for(int i=tid;i<64*32;i+=128){
    int c=i>>5,p=i&31;
    xs[c*36+p]=(xs[c*36+p]-mu[p])*rsd[p]*__ldg(&ln1_g[c]);
  }
  __syncthreads();
  const int o0=(tid&31)*4, p0=(tid>>5)*8;
  const size_t posbase=(size_t)(b*Hn+h)*Wn+w0;
  { // pw1
    float acc[4][8]={};
    gemm<64,4,8>(g_pw1T,128,xs,36,o0,p0,acc);
    float bias[4];
    #pragma unroll
    for(int i2=0;i2<4;i2++) bias[i2]=__ldg(&pw1_b[o0+i2]);
    float* gh=g_h+(size_t)side*H_PER_SIDE+posbase*DW;
    #pragma unroll
    for(int j=0;j<8;j++){
      float v[4];
      #pragma unroll
      for(int i2=0;i2<4;i2++){v[i2]=acc[i2][j]+bias[i2]; hs[(o0+i2)*36+p0+j]=v[i2];}
      *(float4*)&gh[(size_t)(p0+j)*DW+o0]=make_float4(v[0],v[1],v[2],v[3]);
    }
  }
  __syncthreads();
  { // val -> padded buffer
    float acc[4][8]={};
    gemm<128,4,8>(g_valT,128,hs,36,o0,p0,acc);
    float bias[4];
    #pragma unroll
    for(int i2=0;i2<4;i2++) bias[i2]=__ldg(&val_b[o0+i2]);
    float* vp=g_vp+(size_t)side*VP_PER_SIDE+(size_t)b*VP_PER_B;
    #pragma unroll
    for(int j=0;j<8;j++){
      int ww=w0+p0+j+1;
      *(float4*)&vp[((size_t)(h+1)*Wp+ww)*DW+o0]=
        make_float4(acc[0][j]+bias[0],acc[1][j]+bias[1],acc[2][j]+bias[2],acc[3][j]+bias[3]);
    }
  }
}

// K2: depthwise 3x3 + om GEMM (128->108), 16 pos/block
__global__ void __launch_bounds__(128)
k2(const float* __restrict__ dwc_w,const float* __restrict__ dwc_b,
   const float* __restrict__ om_b){
  const int side=blockIdx.z>>1, b=blockIdx.z&1, h=blockIdx.y, w0=blockIdx.x*16;
  const int tid=threadIdx.x;
  __shared__ __align__(16) float ds[128*20];
  {
    int c=tid;
    const float* __restrict__ gh=g_h+(size_t)side*H_PER_SIDE+c;
    float wk[9];
    #pragma unroll
    for(int j=0;j<9;j++) wk[j]=__ldg(&dwc_w[j*128+c]);
    float bias=__ldg(&dwc_b[c]);
    float a[16];
    #pragma unroll
    for(int p=0;p<16;p++) a[p]=bias;
    #pragma unroll
    for(int ky=0;ky<3;ky++){
      int hh=h-1+ky;
      if(hh<0||hh>=Hn) continue;
      const float* rp=gh+(size_t)(b*Hn+hh)*Wn*DW;
      #pragma unroll 4
      for(int p=0;p<16;p++){
        #pragma unroll
        for(int kx=0;kx<3;kx++){
          int ww=w0+p-1+kx;
          if(ww>=0&&ww<Wn) a[p]=fmaf(__ldg(&rp[(size_t)ww*DW]),wk[ky*3+kx],a[p]);
        }
      }
    }
    #pragma unroll
    for(int p=0;p<16;p++) ds[c*20+p]=a[p];
  }
  __syncthreads();
  if(tid<112){
    int o0=(tid%28)*4, p0=(tid/28)*4;
    float acc[4][4]={};
    gemm<128,4,4>(g_omT,112,ds,20,o0,p0,acc);
    if(o0<108){
      float bias[4];
      #pragma unroll
      for(int i2=0;i2<4;i2++) bias[i2]=__ldg(&om_b[o0+i2]);
      size_t posbase=(size_t)(b*Hn+h)*Wn+w0;
      float* go=g_om+(size_t)side*OM_PER_SIDE+posbase*108;
      #pragma unroll
      for(int j=0;j<4;j++)
        *(float4*)&go[(size_t)(p0+j)*108+o0]=
          make_float4(acc[0][j]+bias[0],acc[1][j]+bias[1],acc[2][j]+bias[2],acc[3][j]+bias[3]);
    }
  }
}

// K3: bilinear sampling + outp GEMM + SimpleGate, 16 pos/block
__global__ void __launch_bounds__(128)
k3(const float* __restrict__ outp_b){
  const int side=blockIdx.z>>1, b=blockIdx.z&1, h=blockIdx.y, w0=blockIdx.x*16;
  const int tid=threadIdx.x;
  __shared__ float om_s[16*108];
  __shared__ __align__(16) float4 wtab[576];
  __shared__ __align__(16) int4  atab[576];
  __shared__ __align__(16) float ss[128*20];
  __shared__ __align__(16) float fsm[128*20];
  const size_t posbase=(size_t)(b*Hn+h)*Wn+w0;
  const float* __restrict__ gom=g_om+(size_t)side*OM_PER_SIDE+posbase*108;
  for(int i=tid;i<16*108;i+=128) om_s[i]=gom[i];
  __syncthreads();
  for(int e=tid;e<576;e+=128){
    int p=e/36, gk=e%36, k=gk%9;
    float offx=om_s[p*108+gk*3+0], offy=om_s[p*108+gk*3+1], msk=om_s[p*108+gk*3+2];
    float px=(((float)(w0+p)+1.5f)+(float)(k%3-1))+offx-0.5f;
    float py=(((float)h+1.5f)+(float)(k/3-1))+offy-0.5f;
    float x0f=floorf(px), y0f=floorf(py);
    float tx=px-x0f, ty=py-y0f;
    int x0=(int)x0f, y0=(int)y0f;
    float vx0=(x0>=0&&x0<Wp)?1.f:0.f, vx1=(x0+1>=0&&x0+1<Wp)?1.f:0.f;
    float vy0=(y0>=0&&y0<Hp)?1.f:0.f, vy1=(y0+1>=0&&y0+1<Hp)?1.f:0.f;
    wtab[e]=make_float4((1.f-tx)*(1.f-ty)*msk*vx0*vy0, tx*(1.f-ty)*msk*vx1*vy0,
                        (1.f-tx)*ty*msk*vx0*vy1, tx*ty*msk*vx1*vy1);
    int xc0=min(max(x0,0),Wp-1), xc1=min(max(x0+1,0),Wp-1);
    int yc0=min(max(y0,0),Hp-1), yc1=min(max(y0+1,0),Hp-1);
    atab[e]=make_int4((yc0*Wp+xc0)*DW,(yc0*Wp+xc1)*DW,(yc1*Wp+xc0)*DW,(yc1*Wp+xc1)*DW);
  }
  __syncthreads();
  {
    int c=tid, g=tid>>5;
    const float* __restrict__ vpb=g_vp+(size_t)side*VP_PER_SIDE+(size_t)b*VP_PER_B+c;
    #pragma unroll 2
    for(int p=0;p<16;p++){
      float a=0.f;
      #pragma unroll
      for(int k=0;k<9;k++){
        int e=p*36+g*9+k;
        float4 wv=wtab[e]; int4 av=atab[e];
        a+=wv.x*__ldg(&vpb[av.x])+wv.y*__ldg(&vpb[av.y])
          +wv.z*__ldg(&vpb[av.z])+wv.w*__ldg(&vpb[av.w]);
      }
      ss[c*20+p]=a;
    }
  }
  __syncthreads();
  {
    int o0=(tid&31)*4, p0=(tid>>5)*4;
    float acc[4][4]={};
    gemm<128,4,4>(g_outpT,128,ss,20,o0,p0,acc);
    float bias[4];
    #pragma unroll
    for(int i2=0;i2<4;i2++) bias[i2]=__ldg(&outp_b[o0+i2]);
    #pragma unroll
    for(int i2=0;i2<4;i2++)
      #pragma unroll
      for(int j=0;j<4;j++) fsm[(o0+i2)*20+p0+j]=acc[i2][j]+bias[i2];
  }
  __syncthreads();
  float* gf=g_f+(size_t)side*F_PER_SIDE+posbase*64;
  for(int i=tid;i<16*64;i+=128){
    int p=i>>6,c=i&63;
    gf[i]=fsm[c*20+p]*fsm[(c+64)*20+p];
  }
}

// K4: deterministic partial pooled sums
__global__ void __launch_bounds__(64)
k4(){
  int blk=blockIdx.x, b=blockIdx.y, side=blockIdx.z, c=threadIdx.x;
  size_t base=(size_t)side*F_PER_SIDE+((size_t)b*HW+blk*640)*64+c;
  float s=0.f;
  for(int i=0;i<640;i++) s+=g_f[base+(size_t)i*64];
  g_part[((side*Bn+b)*40+blk)*64+c]=s;
}

// K5: finish pool + channel-attention scale
__global__ void __launch_bounds__(128)
k5(const float* __restrict__ sca_w,const float* __restrict__ sca_b){
  __shared__ float pooled[128];
  int t=threadIdx.x;
  for(int b=0;b<Bn;b++){
    int ss=t>>6,c=t&63;
    float s=0.f;
    for(int k=0;k<40;k++) s+=g_part[((ss*Bn+b)*40+k)*64+c];
    pooled[t]=s*(1.f/(float)HW);
    __syncthreads();
    float acc=__ldg(&sca_b[t]);
    for(int c2=0;c2<128;c2++) acc=fmaf(pooled[c2],__ldg(&sca_w[t*128+c2]),acc);
    g_scale[b*128+t]=acc;
    __syncthreads();
  }
}

// K6: scale -> conv3 -> residual -> LN -> conv4 -> SG -> conv5 -> outputs
__global__ void __launch_bounds__(128)
k6(const float* __restrict__ xl,const float* __restrict__ xr,
   const float* __restrict__ conv3_b,const float* __restrict__ norm2_g,
   const float* __restrict__ conv4_b,const float* __restrict__ conv5_b,
   const float* __restrict__ beta,const float* __restrict__ gamma,
   float* __restrict__ out){
  const int b=blockIdx.z, h=blockIdx.y, w0=blockIdx.x*32, tid=threadIdx.x;
  __shared__ __align__(16) float A[128*36];
  __shared__ __align__(16) float Y1[64*36];
  __shared__ __align__(16) float Y2[64*36];
  __shared__ __align__(16) float S[64*36];
  __shared__ float mu[32],rsd[32];
  const size_t posbase=(size_t)(b*Hn+h)*Wn+w0;
  for(int i=tid;i<32*64;i+=128){
    int p=i>>6,c=i&63;
    A[c*36+p]     =g_f[posbase*64+i]*g_scale[b*128+c];
    A[(64+c)*36+p]=g_f[(size_t)F_PER_SIDE+posbase*64+i]*g_scale[b*128+64+c];
  }
  for(int i=tid;i<64*32;i+=128){
    int c=i>>5,p=i&31;
    size_t a=((size_t)(b*64+c)*Hn+h)*Wn+w0+p;
    Y1[c*36+p]=xl[a]; Y2[c*36+p]=xr[a];
  }
  __syncthreads();
  { // conv3 + residual
    int o0=(tid&31)*2, p0=(tid>>5)*8;
    float acc[2][8]={};
    gemm<128,2,8>(g_c3T,64,A,36,o0,p0,acc);
    float b0=__ldg(&conv3_b[o0]),b1=__ldg(&conv3_b[o0+1]);
    float be0=__ldg(&beta[o0]),be1=__ldg(&beta[o0+1]);
    #pragma unroll
    for(int j=0;j<8;j++){
      float x30=(acc[0][j]+b0)*be0, x31=(acc[1][j]+b1)*be1;
      Y1[o0*36+p0+j]+=x30; Y1[(o0+1)*36+p0+j]+=x31;
      Y2[o0*36+p0+j]+=x30; Y2[(o0+1)*36+p0+j]+=x31;
    }
  }
  __syncthreads();
  if(tid<32){
    float s=0.f,q=0.f;
    #pragma unroll
    for(int c=0;c<64;c++){float v=Y1[c*36+tid];s+=v;q+=v*v;}
    #pragma unroll
    for(int c=0;c<64;c++){float v=Y2[c*36+tid];s+=v;q+=v*v;}
    float m=s*(1.f/128.f), var=q*(1.f/128.f)-m*m;
    mu[tid]=m; rsd[tid]=rsqrtf(var+1e-5f);
  }
  __syncthreads();
  for(int i=tid;i<128*32;i+=128){
    int c=i>>5,p=i&31;
    float v=(c<64)?Y1[c*36+p]:Y2[(c-64)*36+p];
    A[c*36+p]=(v-mu[p])*rsd[p]*__ldg(&norm2_g[c]);
  }
  __syncthreads();
  { // conv4 (in-place on A with sync)
    int o0=(tid&31)*4, p0=(tid>>5)*8;
    float acc[4][8]={};
    gemm<128,4,8>(g_c4T,128,A,36,o0,p0,acc);
    float bias[4];
    #pragma unroll
    for(int i2=0;i2<4;i2++) bias[i2]=__ldg(&conv4_b[o0+i2]);
    __syncthreads();
    #pragma unroll
    for(int i2=0;i2<4;i2++)
      #pragma unroll
      for(int j=0;j<8;j++) A[(o0+i2)*36+p0+j]=acc[i2][j]+bias[i2];
  }
  __syncthreads();
  for(int i=tid;i<64*32;i+=128){
    int c=i>>5,p=i&31;
    S[c*36+p]=A[c*36+p]*A[(c+64)*36+p];
  }
  __syncthreads();
  { // conv5 -> z into A rows 0..63
    int o0=(tid&31)*2, p0=(tid>>5)*8;
    float acc[2][8]={};
    gemm<64,2,8>(g_c5T,64,S,36,o0,p0,acc);
    float b0=__ldg(&conv5_b[o0]),b1=__ldg(&conv5_b[o0+1]);
    __syncthreads();
    #pragma unroll
    for(int j=0;j<8;j++){
      A[o0*36+p0+j]=acc[0][j]+b0;
      A[(o0+1)*36+p0+j]=acc[1][j]+b1;
    }
  }
  __syncthreads();
  for(int i=tid;i<64*32;i+=128){
    int c=i>>5,p=i&31;
    float zg=A[c*36+p]*__ldg(&gamma[c]);
    size_t a=((size_t)(b*64+c)*Hn+h)*Wn+w0+p;
    out[a]=Y1[c*36+p]+zg;
    out[(size_t)Bn*C0*HW+a]=Y2[c*36+p]+zg;
  }
}

extern "C" void kernel_launch(void* const* d_in, const int* in_sizes, int n_in,
                              void* d_out, int out_size){
  const float* xl    =(const float*)d_in[0];
  const float* xr    =(const float*)d_in[1];
  const float* ln1_g =(const float*)d_in[2];
  const float* pw1_w =(const float*)d_in[3];
  const float* pw1_b =(const float*)d_in[4];
  const float* val_w =(const float*)d_in[5];
  const float* val_b =(const float*)d_in[6];
  const float* dwc_w =(const float*)d_in[7];
  const float* dwc_b =(const float*)d_in[8];
  const float* om_w  =(const float*)d_in[9];
  const float* om_b  =(const float*)d_in[10];
  const float* outp_w=(const float*)d_in[11];
  const float* outp_b=(const float*)d_in[12];
  const float* sca_w =(const float*)d_in[13];
  const float* sca_b =(const float*)d_in[14];
  const float* c3_w  =(const float*)d_in[15];
  const float* c3_b  =(const float*)d_in[16];
  const float* n2_g  =(const float*)d_in[17];
  const float* c4_w  =(const float*)d_in[18];
  const float* c4_b  =(const float*)d_in[19];
  const float* c5_w  =(const float*)d_in[20];
  const float* c5_b  =(const float*)d_in[21];
  const float* beta  =(const float*)d_in[22];
  const float* gamma =(const float*)d_in[23];
  float* out=(float*)d_out;

  prep_kernel<<<(83968+255)/256,256>>>(pw1_w,val_w,om_w,outp_w,c3_w,c4_w,c5_w);
  zero_borders_kernel<<<(4*644*128+255)/256,256>>>();
  k1<<<dim3(5,160,4),128>>>(xl,xr,ln1_g,pw1_b,val_b);
  k2<<<dim3(10,160,4),128>>>(dwc_w,dwc_b,om_b);
  k3<<<dim3(10,160,4),128>>>(outp_b);
  k4<<<dim3(40,2,2),64>>>();
  k5<<<1,128>>>(sca_w,sca_b);
  k6<<<dim3(5,160,2),128>>>(xl,xr,c3_b,n2_g,c4_b,c5_b,beta,gamma,out);
}